// round 3
// baseline (speedup 1.0000x reference)
#include <cuda_runtime.h>

// FittedRankOneRNN rank-2 state decomposition:
//   x_t = p_t*m + q_t*wi  (two scalars per batch)
//   q_{t} = 0.8 q_{t-1} + 0.2 u_{t-1}
//   p_{t+1} = 0.8 p_t + 0.2 kappa_t,  kappa_t = (1/N) sum tanh(p_t m + q_t wi) . n
//   z_{t-1} = (1/N) sum tanh(p_t m + q_t wi) . w   (same tanh vector)
// tanh via ex2+rcp (branch-free, ~1e-7 acc):  t = ex2(2x*log2e); tanh = (t-1)*rcp(t+1)
// The 2*log2e scale is folded into m and wi at load time.
// NOTE: bench ptxas target is plain sm_100 -> no redux.sync.add.f32; use shfl butterfly.

#define TPB 256
#define EPT 4   // 256*4 = N = 1024

__device__ __forceinline__ float ex2_approx(float x) {
    float r; asm("ex2.approx.f32 %0, %1;" : "=f"(r) : "f"(x)); return r;
}
__device__ __forceinline__ float rcp_approx(float x) {
    float r; asm("rcp.approx.f32 %0, %1;" : "=f"(r) : "f"(x)); return r;
}

__global__ __launch_bounds__(TPB)
void rank1_rnn_kernel(const float* __restrict__ gu,
                      const float* __restrict__ gm,
                      const float* __restrict__ gn,
                      const float* __restrict__ gwi,
                      const float* __restrict__ gw,
                      float* __restrict__ gz,
                      int T)
{
    __shared__ float  s_u[1024];         // input row (T=1000)
    __shared__ float  s_z[1024];         // output row buffer
    __shared__ float4 s_part[2][4];      // [buf][warp-pair]: 8 warps x float2(an,aw)

    const int b    = blockIdx.x;
    const int tid  = threadIdx.x;
    const int lane = tid & 31;
    const int warp = tid >> 5;

    for (int i = tid; i < T; i += TPB) s_u[i] = gu[b * T + i];

    // Weights in registers; fold 2*log2(e) into m and wi so the state FMA
    // directly produces the ex2 argument.
    const float C = 2.8853900817779268f;  // 2*log2(e)
    float rm[EPT], rwi[EPT], rn[EPT], rw[EPT];
#pragma unroll
    for (int e = 0; e < EPT; e++) {
        const int i = tid + e * TPB;
        rm[e]  = gm[i]  * C;
        rwi[e] = gwi[i] * C;
        rn[e]  = gn[i];
        rw[e]  = gw[i];
    }
    __syncthreads();

    const float BETA   = 0.8f;
    const float ALPHA  = 0.2f;
    const float INV_N  = 1.0f / 1024.0f;
    const float KSCALE = ALPHA * INV_N;

    float p = 0.0f, q = 0.0f;
    int buf = 0;

    for (int t = 1; t <= T; t++) {
        // q chain is input-only: off the p critical path.
        q = fmaf(BETA, q, ALPHA * s_u[t - 1]);

        float an0 = 0.f, aw0 = 0.f, an1 = 0.f, aw1 = 0.f;
#pragma unroll
        for (int e = 0; e < EPT; e++) {
            const float s  = fmaf(p, rm[e], q * rwi[e]);   // = 2*log2e * x
            const float tt = ex2_approx(s);                 // e^{2x}
            const float r  = (tt - 1.0f) * rcp_approx(tt + 1.0f);  // tanh(x)
            if (e & 1) { an1 = fmaf(r, rn[e], an1); aw1 = fmaf(r, rw[e], aw1); }
            else       { an0 = fmaf(r, rn[e], an0); aw0 = fmaf(r, rw[e], aw0); }
        }
        float an = an0 + an1;
        float aw = aw0 + aw1;

        // Interleaved dual butterfly: the two chains are independent, so each
        // stage's shuffles pipeline; effective latency ~ one chain.
#pragma unroll
        for (int off = 16; off; off >>= 1) {
            const float sn = __shfl_xor_sync(0xffffffffu, an, off);
            const float sw = __shfl_xor_sync(0xffffffffu, aw, off);
            an += sn;
            aw += sw;
        }

        if (lane == 0)
            ((float2*)s_part[buf])[warp] = make_float2(an, aw);
        __syncthreads();   // one barrier per step (double-buffered partials)

        const float4 v0 = s_part[buf][0];
        const float4 v1 = s_part[buf][1];
        const float4 v2 = s_part[buf][2];
        const float4 v3 = s_part[buf][3];
        const float kap = ((v0.x + v0.z) + (v1.x + v1.z))
                        + ((v2.x + v2.z) + (v3.x + v3.z));
        const float zz  = ((v0.y + v0.w) + (v1.y + v1.w))
                        + ((v2.y + v2.w) + (v3.y + v3.w));

        if (tid == 0) s_z[t - 1] = zz * INV_N;
        p = fmaf(BETA, p, kap * KSCALE);
        buf ^= 1;
    }

    __syncthreads();
    for (int i = tid; i < T; i += TPB) gz[b * T + i] = s_z[i];
}

extern "C" void kernel_launch(void* const* d_in, const int* in_sizes, int n_in,
                              void* d_out, int out_size)
{
    const float* u  = (const float*)d_in[0];
    const float* m  = (const float*)d_in[1];
    const float* n  = (const float*)d_in[2];
    const float* wi = (const float*)d_in[3];
    const float* w  = (const float*)d_in[4];
    float* z = (float*)d_out;

    const int T = 1000;
    const int B = out_size / T;   // 256
    rank1_rnn_kernel<<<B, TPB>>>(u, m, n, wi, w, z, T);
}